// round 1
// baseline (speedup 1.0000x reference)
#include <cuda_runtime.h>
#include <math.h>

// Problem constants
#define NYg    256
#define PMLc   20
#define PADc   22          // PML + FD_PAD
#define NP     300         // NYP == NXP
#define SXc    320         // padded row stride (floats)
#define Gc     4           // zero guard ring width
#define ARc    (NP + 2*Gc) // 308 rows allocated
#define Fc     (ARc*SXc)   // floats per field = 98560
#define NTc    250
#define NSHOTc 2
#define NSRCc  8
#define NRECc  64

#define DTc 0.0005f
#define Hc  5.0f

// Persistent-kernel config
#define NCTA 120
#define TPB  320
#define CPS  (NCTA/NSHOTc)  // 60 CTAs per shot
#define RPC  (NP/CPS)       // 5 rows per CTA

// Field layout inside g_state (units of Fc):
//  0..3 : wave buffers  w[shot][buf]
//  4..5 : psiy[shot]    6..7 : psix[shot]
//  8..9 : zetay[shot]  10..11: zetax[shot]
//  12   : v2dt2 (shared across shots)
__device__ float g_state[13*Fc];
__device__ float g_a[NP];
__device__ float g_b[NP];
__device__ unsigned g_barcnt;
__device__ volatile unsigned g_barsense;

__device__ __forceinline__ int IDX(int y, int x) { return (y+Gc)*SXc + (x+Gc); }

// Sense-reversing grid barrier (requires all NCTA CTAs co-resident; NCTA=120 <= 148 SMs)
__device__ __forceinline__ void gbar(unsigned ph) {
    __syncthreads();
    if (threadIdx.x == 0) {
        __threadfence();  // release: make prior stores visible at L2
        if (atomicAdd(&g_barcnt, 1u) == (unsigned)(NCTA - 1)) {
            g_barcnt = 0u;
            __threadfence();
            g_barsense = ph;           // release the grid
        } else {
            while (g_barsense != ph) { /* spin on L2 */ }
        }
        __threadfence();  // acquire
    }
    __syncthreads();
}

extern "C" __global__ void __launch_bounds__(TPB)
wave_kernel(const float* __restrict__ v,
            const float* __restrict__ amp,
            const void*  __restrict__ sloc,
            const void*  __restrict__ rloc,
            float* __restrict__ out)
{
    const int cta = blockIdx.x, tid = threadIdx.x;
    const int gt = cta*TPB + tid, GT = NCTA*TPB;

    // ---------------- init phase (every launch: deterministic) ----------------
    // Zero all mutable state (fields 0..11). v2dt2 (field 12) fully written below.
    for (int i = gt; i < 12*Fc; i += GT) g_state[i] = 0.0f;

    // C-PML profiles (NYP == NXP and DY == DX -> one pair of arrays)
    for (int i = gt; i < NP; i += GT) {
        float fi = (float)i;
        float frac = fmaxf((float)PADc - fi, fi - (float)(NP - PADc - 1)) / (float)PMLc;
        frac = fminf(fmaxf(frac, 0.0f), 1.0f);
        float smax = 3.0f * 4000.0f * logf(1000.0f) / (2.0f * (float)PMLc * Hc);
        float sig  = smax * frac * frac;
        float alp  = 3.14159265358979f * 25.0f * (1.0f - frac);
        float bb   = expf(-(sig + alp) * DTc);
        g_b[i] = bb;
        g_a[i] = sig / (sig + alp + 1e-9f) * (bb - 1.0f);
    }

    // v2dt2 = (edge-padded v)^2 * dt^2 over the interior NPxNP
    for (int i = gt; i < NP*NP; i += GT) {
        int y = i / NP, x = i - y*NP;
        int vy = min(max(y - PADc, 0), NYg - 1);
        int vx = min(max(x - PADc, 0), NYg - 1);
        float vv = v[vy*NYg + vx];
        g_state[12*Fc + IDX(y,x)] = vv * vv * (DTc*DTc);
    }

    const int shot = cta / CPS;
    const int y0   = (cta % CPS) * RPC;

    __shared__ int   sh_key[NSRCc];
    __shared__ float sh_scale[NSRCc];
    __shared__ int   sh_ridx[NSHOTc*NRECc];

    // Decode source locations (int64-vs-int32 heuristic: high words all zero => int64)
    if (tid < NSRCc) {
        const unsigned* w32 = (const unsigned*)sloc;
        bool is64 = true;
        for (int i = 1; i < NSHOTc*NSRCc*2; i += 2)
            if (w32[i] != 0u) { is64 = false; break; }
        int e = (shot*NSRCc + tid) * 2;
        int sy, sx;
        if (is64) { sy = (int)w32[2*e]; sx = (int)w32[2*(e+1)]; }
        else      { const int* w = (const int*)sloc; sy = w[e]; sx = w[e+1]; }
        float vv = v[sy*NYg + sx];
        sh_key[tid]   = ((sy + PADc) << 9) | (sx + PADc);
        sh_scale[tid] = vv * vv * (DTc*DTc);
    }
    // Decode receiver locations (CTA 0 records)
    if (cta == 0 && tid < NSHOTc*NRECc) {
        const unsigned* w32 = (const unsigned*)rloc;
        bool is64 = true;
        for (int i = 1; i < NSHOTc*NRECc*2; i += 2)
            if (w32[i] != 0u) { is64 = false; break; }
        int e = tid * 2;
        int ry, rx;
        if (is64) { ry = (int)w32[2*e]; rx = (int)w32[2*(e+1)]; }
        else      { const int* w = (const int*)rloc; ry = w[e]; rx = w[e+1]; }
        sh_ridx[tid] = IDX(ry + PADc, rx + PADc);
    }

    unsigned ph = 0;
    gbar(++ph);   // init complete, visible everywhere

    // ---------------- time loop ----------------
    float* psiy = g_state + (4 + shot)*Fc;
    float* psix = g_state + (6 + shot)*Fc;
    float* zy   = g_state + (8 + shot)*Fc;
    float* zx   = g_state + (10 + shot)*Fc;
    const float* v2 = g_state + 12*Fc;
    float* wbase = g_state + shot*2*Fc;
    const float* amp_s = amp + shot*NSRCc*NTc;

    const float iH  = 1.0f / Hc;
    const float iH2 = 1.0f / (Hc*Hc);
    const float C1A =  0.66666666666666666f, C1B = -0.08333333333333333f;
    const float C2A =  1.33333333333333333f, C2B = -0.08333333333333333f, C2C = -2.5f;

    int cur = 0;
    const int  x   = tid;
    const bool act = (tid < NP);

    float d2ys[RPC], d2xs[RPC];  // per-thread register stash between stages

    for (int t = 0; t < NTc; t++) {
        const float* wfc  = wbase + cur*Fc;
        float*       wold = wbase + (cur^1)*Fc;

        // -------- Stage A: FD of wfc, update psi --------
        #pragma unroll
        for (int r = 0; r < RPC; r++) {
            int y = y0 + r;
            if (act) {
                int p = IDX(y, x);
                float wc = wfc[p];
                // y-taps may cross CTA boundaries -> L2 (.cg) for coherence
                float a1 = __ldcg(wfc + p - SXc),   a2 = __ldcg(wfc + p + SXc);
                float a3 = __ldcg(wfc + p - 2*SXc), a4 = __ldcg(wfc + p + 2*SXc);
                // x-taps stay inside this CTA's own rows -> L1 ok
                float b1 = wfc[p-1], b2 = wfc[p+1], b3 = wfc[p-2], b4 = wfc[p+2];
                float dwdy = (C1A*(a2 - a1) + C1B*(a4 - a3)) * iH;
                float dwdx = (C1A*(b2 - b1) + C1B*(b4 - b3)) * iH;
                float d2y  = (C2C*wc + C2A*(a1 + a2) + C2B*(a3 + a4)) * iH2;
                float d2x  = (C2C*wc + C2A*(b1 + b2) + C2B*(b3 + b4)) * iH2;
                float ayv = g_a[y], byv = g_b[y], axv = g_a[x], bxv = g_b[x];
                psiy[p] = byv*psiy[p] + ayv*dwdy;
                psix[p] = bxv*psix[p] + axv*dwdx;
                d2ys[r] = d2y; d2xs[r] = d2x;
            }
        }
        gbar(++ph);  // all psi updated before taking their derivatives

        // -------- Stage B: FD of psi, update zeta, time step, sources --------
        #pragma unroll
        for (int r = 0; r < RPC; r++) {
            int y = y0 + r;
            bool srow = false;
            #pragma unroll
            for (int j = 0; j < NSRCc; j++) srow = srow || ((sh_key[j] >> 9) == y);
            if (act) {
                int p = IDX(y, x);
                float a1 = __ldcg(psiy + p - SXc),   a2 = __ldcg(psiy + p + SXc);
                float a3 = __ldcg(psiy + p - 2*SXc), a4 = __ldcg(psiy + p + 2*SXc);
                float dpy = (C1A*(a2 - a1) + C1B*(a4 - a3)) * iH;
                float b1 = psix[p-1], b2 = psix[p+1], b3 = psix[p-2], b4 = psix[p+2];
                float dpx = (C1A*(b2 - b1) + C1B*(b4 - b3)) * iH;
                float ayv = g_a[y], byv = g_b[y], axv = g_a[x], bxv = g_b[x];
                float zyv = byv*zy[p] + ayv*(d2ys[r] + dpy); zy[p] = zyv;
                float zxv = bxv*zx[p] + axv*(d2xs[r] + dpx); zx[p] = zxv;
                float lap = d2ys[r] + d2xs[r] + dpy + dpx + zyv + zxv;
                float wnew = 2.0f*wfc[p] - wold[p] + v2[p]*lap;
                if (srow) {
                    int key = (y << 9) | x;
                    #pragma unroll
                    for (int j = 0; j < NSRCc; j++)
                        if (sh_key[j] == key) wnew += sh_scale[j] * amp_s[j*NTc + t];
                }
                wold[p] = wnew;
            }
        }
        gbar(++ph);  // wfp complete (incl. sources) before recording / next step

        // -------- record receivers (CTA 0; others proceed into next Stage A,
        // which never writes the buffer being recorded) --------
        if (cta == 0 && tid < NSHOTc*NRECc) {
            int s = tid >> 6, rr = tid & 63;
            out[(s*NRECc + rr)*NTc + t] =
                __ldcg(g_state + (s*2 + (cur^1))*Fc + sh_ridx[tid]);
        }
        cur ^= 1;
    }
}

extern "C" void kernel_launch(void* const* d_in, const int* in_sizes, int n_in,
                              void* d_out, int out_size)
{
    const float* v    = (const float*)d_in[0];
    const float* amp  = (const float*)d_in[1];
    const void*  sloc = d_in[2];
    const void*  rloc = d_in[3];
    wave_kernel<<<NCTA, TPB>>>(v, amp, sloc, rloc, (float*)d_out);
}

// round 2
// speedup vs baseline: 1.8233x; 1.8233x over previous
#include <cuda_runtime.h>
#include <math.h>

// Problem constants
#define NYg    256
#define PMLc   20
#define PADc   22          // PML + FD_PAD
#define NP     300         // NYP == NXP
#define SXc    320         // padded row stride (floats)
#define Gc     4           // zero guard ring width
#define ARc    (NP + 2*Gc) // 308 rows allocated
#define Fc     (ARc*SXc)   // floats per field = 98560
#define NTc    250
#define NSHOTc 2
#define NSRCc  8
#define NRECc  64

#define DTc 0.0005f
#define Hc  5.0f

// Persistent-kernel config
#define NCTA 120
#define TPB  320
#define CPS  (NCTA/NSHOTc)  // 60 CTAs per shot
#define RPC  (NP/CPS)       // 5 rows per CTA
#define HR   (RPC+4)        // 9 psiy rows (owned + 2 halo each side)
#define CR   (RPC+8)        // 13 wfc column rows

// Per-shot fields: w0,w1,py0,py1 (psix in smem, zeta/wfm in regs). v2 shared.
// layout: shot s -> fields s*4 + {0,1,2,3};  v2 -> field 8
__device__ float g_state[9*Fc];
__device__ float g_a[NP];
__device__ float g_b[NP];
__device__ volatile unsigned g_arr[NCTA];
__device__ volatile unsigned g_sense;

__device__ __forceinline__ int IDX(int y, int x) { return (y+Gc)*SXc + (x+Gc); }

// Grid barrier: distributed arrival (one flag per CTA, no atomics),
// central release by CTA 0. Equality tests are safe across graph replays:
// stale values from a previous launch can never equal the fresh ph sequence
// until the owner writes it, and a slot cannot advance past ph before CTA 0
// has observed it (CTAs are blocked on g_sense until CTA 0 releases).
__device__ __forceinline__ void gbar(int cta, unsigned ph) {
    __syncthreads();
    __threadfence();   // release
    if (cta == 0) {
        if (threadIdx.x > 0 && threadIdx.x < NCTA) {
            while (g_arr[threadIdx.x] != ph) { }
        }
        __syncthreads();            // all pollers done
        if (threadIdx.x == 0) g_sense = ph;
    } else {
        if (threadIdx.x == 0) {
            g_arr[cta] = ph;
            while (g_sense != ph) { }
        }
    }
    __threadfence();   // acquire
    __syncthreads();
}

extern "C" __global__ void __launch_bounds__(TPB)
wave_kernel(const float* __restrict__ v,
            const float* __restrict__ amp,
            const void*  __restrict__ sloc,
            const void*  __restrict__ rloc,
            float* __restrict__ out)
{
    const int cta = blockIdx.x, tid = threadIdx.x;
    const int gt = cta*TPB + tid, GT = NCTA*TPB;

    // ---------------- init (every launch: deterministic) ----------------
    for (int i = gt; i < 8*Fc; i += GT) g_state[i] = 0.0f;   // wave + psiy bufs

    for (int i = gt; i < NP; i += GT) {
        float fi = (float)i;
        float frac = fmaxf((float)PADc - fi, fi - (float)(NP - PADc - 1)) / (float)PMLc;
        frac = fminf(fmaxf(frac, 0.0f), 1.0f);
        float smax = 3.0f * 4000.0f * logf(1000.0f) / (2.0f * (float)PMLc * Hc);
        float sig  = smax * frac * frac;
        float alp  = 3.14159265358979f * 25.0f * (1.0f - frac);
        float bb   = expf(-(sig + alp) * DTc);
        g_b[i] = bb;
        g_a[i] = sig / (sig + alp + 1e-9f) * (bb - 1.0f);
    }

    for (int i = gt; i < NP*NP; i += GT) {
        int y = i / NP, x = i - y*NP;
        int vy = min(max(y - PADc, 0), NYg - 1);
        int vx = min(max(x - PADc, 0), NYg - 1);
        float vv = v[vy*NYg + vx];
        g_state[8*Fc + IDX(y,x)] = vv * vv * (DTc*DTc);
    }

    const int shot = cta / CPS;
    const int y0   = (cta % CPS) * RPC;

    __shared__ int   sh_key[NSRCc];
    __shared__ float sh_scale[NSRCc];
    __shared__ int   sh_ridx[NSHOTc*NRECc];
    __shared__ float psix_s[RPC][SXc];   // persistent psix state (x-guards = 0)

    for (int i = tid; i < RPC*SXc; i += TPB) ((float*)psix_s)[i] = 0.0f;

    if (tid < NSRCc) {
        const unsigned* w32 = (const unsigned*)sloc;
        bool is64 = true;
        for (int i = 1; i < NSHOTc*NSRCc*2; i += 2)
            if (w32[i] != 0u) { is64 = false; break; }
        int e = (shot*NSRCc + tid) * 2;
        int sy, sx;
        if (is64) { sy = (int)w32[2*e]; sx = (int)w32[2*(e+1)]; }
        else      { const int* w = (const int*)sloc; sy = w[e]; sx = w[e+1]; }
        float vv = v[sy*NYg + sx];
        sh_key[tid]   = ((sy + PADc) << 9) | (sx + PADc);
        sh_scale[tid] = vv * vv * (DTc*DTc);
    }
    if (cta == 0 && tid < NSHOTc*NRECc) {
        const unsigned* w32 = (const unsigned*)rloc;
        bool is64 = true;
        for (int i = 1; i < NSHOTc*NRECc*2; i += 2)
            if (w32[i] != 0u) { is64 = false; break; }
        int e = tid * 2;
        int ry, rx;
        if (is64) { ry = (int)w32[2*e]; rx = (int)w32[2*(e+1)]; }
        else      { const int* w = (const int*)rloc; ry = w[e]; rx = w[e+1]; }
        sh_ridx[tid] = IDX(ry + PADc, rx + PADc);
    }

    unsigned ph = 0;
    gbar(cta, ++ph);   // init visible everywhere

    // ---------------- per-thread setup ----------------
    float* wbase  = g_state + shot*4*Fc;
    float* pybase = wbase + 2*Fc;
    const float* v2 = g_state + 8*Fc;
    const float* amp_s = amp + shot*NSRCc*NTc;

    const float iH  = 1.0f / Hc;
    const float iH2 = 1.0f / (Hc*Hc);
    const float C1A =  0.66666666666666666f, C1B = -0.08333333333333333f;
    const float C2A =  1.33333333333333333f, C2B = -0.08333333333333333f, C2C = -2.5f;

    const int  x   = tid;
    const bool act = (tid < NP);

    // Coefficients for rows y0-2 .. y0+6 (halo included), x coeffs scalar
    float ayr[HR], byr[HR];
    #pragma unroll
    for (int r = 0; r < HR; r++) {
        int y = y0 - 2 + r;
        bool in = (y >= 0 && y < NP);
        ayr[r] = in ? g_a[y] : 0.0f;
        byr[r] = in ? g_b[y] : 0.0f;
    }
    const float axv = act ? g_a[x] : 0.0f;
    const float bxv = act ? g_b[x] : 0.0f;

    // Which owned rows host sources (constant over time)
    bool srow[RPC];
    #pragma unroll
    for (int r2 = 0; r2 < RPC; r2++) {
        bool s = false;
        #pragma unroll
        for (int j = 0; j < NSRCc; j++) s = s || ((sh_key[j] >> 9) == (y0 + r2));
        srow[r2] = s;
    }

    // Register-resident state
    float psr[RPC], zyr[RPC], zxr[RPC], wold[RPC];
    #pragma unroll
    for (int r2 = 0; r2 < RPC; r2++) { psr[r2]=0.f; zyr[r2]=0.f; zxr[r2]=0.f; wold[r2]=0.f; }

    int cur = 0;

    // ---------------- time loop: ONE grid barrier per step ----------------
    for (int t = 0; t < NTc; t++) {
        const float* wfc = wbase + cur*Fc;
        float*       wst = wbase + (cur^1)*Fc;
        const int pb = t & 1;
        const float* pyold = pybase + (pb^1)*Fc;
        float*       pynew = pybase + pb*Fc;

        float s1[RPC], s2[RPC], cen[RPC];

        if (act) {
            // Column of wfc at this x: rows y0-4 .. y0+8 (13 independent L2 loads)
            float c[CR];
            #pragma unroll
            for (int k = 0; k < CR; k++)
                c[k] = __ldcg(wfc + IDX(y0 - 4 + k, x));

            // psiy update for 9 rows (owned + recomputed halo)
            float py[HR];
            #pragma unroll
            for (int r = 0; r < HR; r++) {
                int y = y0 - 2 + r;
                float dwdy = (C1A*(c[r+3]-c[r+1]) + C1B*(c[r+4]-c[r])) * iH;
                float po;
                if (r >= 2 && r <= 6) po = psr[r-2];
                else po = (y >= 0 && y < NP) ? __ldcg(pyold + IDX(y, x)) : 0.0f;
                float pn = byr[r]*po + ayr[r]*dwdy;
                if (y < 0 || y >= NP) pn = 0.0f;
                py[r] = pn;
            }
            #pragma unroll
            for (int r2 = 0; r2 < RPC; r2++) {
                psr[r2] = py[r2+2];
                pynew[IDX(y0 + r2, x)] = py[r2+2];
            }

            // Owned rows: second derivatives, dpsiydy, psix update (smem)
            #pragma unroll
            for (int r2 = 0; r2 < RPC; r2++) {
                int m = r2 + 4;
                int p = IDX(y0 + r2, x);
                float b1 = wfc[p-1], b2 = wfc[p+1], b3 = wfc[p-2], b4 = wfc[p+2];
                float d2y  = (C2C*c[m] + C2A*(c[m-1]+c[m+1]) + C2B*(c[m-2]+c[m+2])) * iH2;
                float d2x  = (C2C*c[m] + C2A*(b1+b2)       + C2B*(b3+b4))         * iH2;
                float dwdx = (C1A*(b2-b1) + C1B*(b4-b3)) * iH;
                float dpy  = (C1A*(py[r2+3]-py[r2+1]) + C1B*(py[r2+4]-py[r2])) * iH;
                float pxn  = bxv*psix_s[r2][x+4] + axv*dwdx;
                psix_s[r2][x+4] = pxn;
                s1[r2] = d2y + dpy;
                s2[r2] = d2x;
                cen[r2] = c[m];
            }
        }
        __syncthreads();   // psix taps ready

        if (act) {
            #pragma unroll
            for (int r2 = 0; r2 < RPC; r2++) {
                int y = y0 + r2;
                int p = IDX(y, x);
                float dpx = (C1A*(psix_s[r2][x+5]-psix_s[r2][x+3])
                           + C1B*(psix_s[r2][x+6]-psix_s[r2][x+2])) * iH;
                float ayv = ayr[r2+2], byv = byr[r2+2];
                float zyv = byv*zyr[r2] + ayv*s1[r2];             zyr[r2] = zyv;
                float zxv = bxv*zxr[r2] + axv*(s2[r2] + dpx);     zxr[r2] = zxv;
                float lap = s1[r2] + s2[r2] + dpx + zyv + zxv;
                float wnew = 2.0f*cen[r2] - wold[r2] + v2[p]*lap;
                if (srow[r2]) {
                    int key = (y << 9) | x;
                    #pragma unroll
                    for (int j = 0; j < NSRCc; j++)
                        if (sh_key[j] == key) wnew += sh_scale[j] * amp_s[j*NTc + t];
                }
                wold[r2] = cen[r2];
                wst[p] = wnew;
            }
        }

        gbar(cta, ++ph);   // step complete everywhere

        if (cta == 0 && tid < NSHOTc*NRECc) {
            int s = tid >> 6, rr = tid & 63;
            out[(s*NRECc + rr)*NTc + t] =
                __ldcg(g_state + (s*4 + (cur^1))*Fc + sh_ridx[tid]);
        }
        cur ^= 1;
    }
}

extern "C" void kernel_launch(void* const* d_in, const int* in_sizes, int n_in,
                              void* d_out, int out_size)
{
    const float* v    = (const float*)d_in[0];
    const float* amp  = (const float*)d_in[1];
    const void*  sloc = d_in[2];
    const void*  rloc = d_in[3];
    wave_kernel<<<NCTA, TPB>>>(v, amp, sloc, rloc, (float*)d_out);
}

// round 3
// speedup vs baseline: 2.2075x; 1.2107x over previous
#include <cuda_runtime.h>
#include <math.h>

// Problem constants
#define NYg    256
#define PMLc   20
#define PADc   22          // PML + FD_PAD
#define NP     300         // NYP == NXP
#define SXc    320         // padded row stride (floats)
#define Gc     4           // zero guard ring width
#define ARc    (NP + 2*Gc) // 308 rows allocated
#define Fc     (ARc*SXc)   // floats per field = 98560
#define NTc    250
#define NSHOTc 2
#define NSRCc  8
#define NRECc  64

#define DTc 0.0005f
#define Hc  5.0f

// Persistent-kernel config
#define NCTA 120
#define TPB  320
#define CPS  (NCTA/NSHOTc)  // 60 CTAs per shot
#define RPC  (NP/CPS)       // 5 rows per CTA
#define HR   (RPC+4)        // 9 psiy rows (owned + 2 halo each side)
#define CR   (RPC+8)        // 13 wfc column rows

// Per-shot fields: w0,w1,py0,py1 (psix in smem, zeta/wfm in regs). v2 -> field 8
__device__ float g_state[9*Fc];
__device__ float g_a[NP];
__device__ float g_b[NP];
__device__ unsigned g_arr[NCTA];
__device__ unsigned g_sense;

__device__ __forceinline__ int IDX(int y, int x) { return (y+Gc)*SXc + (x+Gc); }

__device__ __forceinline__ unsigned ld_rlx(const unsigned* p) {
    unsigned v;
    asm volatile("ld.relaxed.gpu.u32 %0, [%1];" : "=r"(v) : "l"(p));
    return v;
}
__device__ __forceinline__ void st_rlx(unsigned* p, unsigned v) {
    asm volatile("st.relaxed.gpu.u32 [%0], %1;" :: "l"(p), "r"(v) : "memory");
}
__device__ __forceinline__ void fence_gpu() {
    asm volatile("fence.acq_rel.gpu;" ::: "memory");
}

// Grid barrier. Distributed arrival flags (one per CTA), central release by
// CTA 0. All gpu-scope fences executed by ONE thread per CTA; cumulativity of
// fence.acq_rel.gpu + __syncthreads() extends release/acquire to the whole CTA
// (same construction as cooperative-groups grid.sync).
// Phase-equality is replay-safe: stale values from a previous launch can only
// equal the final phase, by which time the slot has been rewritten this
// launch; a slot cannot advance past phase ph before CTA 0 observed ph.
__device__ __forceinline__ void gbar(int cta, unsigned ph) {
    __syncthreads();
    if (cta == 0) {
        if (threadIdx.x >= 1 && threadIdx.x < NCTA) {
            while (ld_rlx(&g_arr[threadIdx.x]) != ph) { }
        }
        __syncthreads();                    // all arrivals observed
        if (threadIdx.x == 0) {
            fence_gpu();                    // release own writes + acquire observed
            st_rlx(&g_sense, ph);
        }
        __syncthreads();
    } else {
        if (threadIdx.x == 0) {
            fence_gpu();                    // release this CTA's writes
            st_rlx(&g_arr[cta], ph);
            while (ld_rlx(&g_sense) != ph) { }
            fence_gpu();                    // acquire
        }
        __syncthreads();
    }
}

extern "C" __global__ void __launch_bounds__(TPB)
wave_kernel(const float* __restrict__ v,
            const float* __restrict__ amp,
            const void*  __restrict__ sloc,
            const void*  __restrict__ rloc,
            float* __restrict__ out)
{
    const int cta = blockIdx.x, tid = threadIdx.x;
    const int gt = cta*TPB + tid, GT = NCTA*TPB;

    // ---------------- init (every launch: deterministic) ----------------
    for (int i = gt; i < 8*Fc; i += GT) g_state[i] = 0.0f;   // wave + psiy bufs

    for (int i = gt; i < NP; i += GT) {
        float fi = (float)i;
        float frac = fmaxf((float)PADc - fi, fi - (float)(NP - PADc - 1)) / (float)PMLc;
        frac = fminf(fmaxf(frac, 0.0f), 1.0f);
        float smax = 3.0f * 4000.0f * logf(1000.0f) / (2.0f * (float)PMLc * Hc);
        float sig  = smax * frac * frac;
        float alp  = 3.14159265358979f * 25.0f * (1.0f - frac);
        float bb   = expf(-(sig + alp) * DTc);
        g_b[i] = bb;
        g_a[i] = sig / (sig + alp + 1e-9f) * (bb - 1.0f);
    }

    for (int i = gt; i < NP*NP; i += GT) {
        int y = i / NP, x = i - y*NP;
        int vy = min(max(y - PADc, 0), NYg - 1);
        int vx = min(max(x - PADc, 0), NYg - 1);
        float vv = v[vy*NYg + vx];
        g_state[8*Fc + IDX(y,x)] = vv * vv * (DTc*DTc);
    }

    const int shot = cta / CPS;
    const int y0   = (cta % CPS) * RPC;

    __shared__ int   sh_key[NSRCc];
    __shared__ float sh_scale[NSRCc];
    __shared__ float psix_s[RPC][SXc];   // persistent psix state (x-guards = 0)
    __shared__ int   sh_rn;
    __shared__ int   sh_rr2[NRECc];      // local row index of receiver
    __shared__ int   sh_rx[NRECc];       // padded x of receiver
    __shared__ int   sh_ro[NRECc];       // output row index (shot*NREC + rec)

    for (int i = tid; i < RPC*SXc; i += TPB) ((float*)psix_s)[i] = 0.0f;

    if (tid < NSRCc) {
        const unsigned* w32 = (const unsigned*)sloc;
        bool is64 = true;
        for (int i = 1; i < NSHOTc*NSRCc*2; i += 2)
            if (w32[i] != 0u) { is64 = false; break; }
        int e = (shot*NSRCc + tid) * 2;
        int sy, sx;
        if (is64) { sy = (int)w32[2*e]; sx = (int)w32[2*(e+1)]; }
        else      { const int* w = (const int*)sloc; sy = w[e]; sx = w[e+1]; }
        float vv = v[sy*NYg + sx];
        sh_key[tid]   = ((sy + PADc) << 9) | (sx + PADc);
        sh_scale[tid] = vv * vv * (DTc*DTc);
    }
    // Receivers owned by this CTA (row within [y0, y0+RPC) of this shot)
    if (tid == 0) {
        const unsigned* w32 = (const unsigned*)rloc;
        bool is64 = true;
        for (int i = 1; i < NSHOTc*NRECc*2; i += 2)
            if (w32[i] != 0u) { is64 = false; break; }
        int n = 0;
        for (int rr = 0; rr < NRECc; rr++) {
            int e = (shot*NRECc + rr) * 2;
            int ry, rx;
            if (is64) { ry = (int)w32[2*e]; rx = (int)w32[2*(e+1)]; }
            else      { const int* w = (const int*)rloc; ry = w[e]; rx = w[e+1]; }
            int yp = ry + PADc;
            if (yp >= y0 && yp < y0 + RPC) {
                sh_rr2[n] = yp - y0;
                sh_rx[n]  = rx + PADc;
                sh_ro[n]  = shot*NRECc + rr;
                n++;
            }
        }
        sh_rn = n;
    }

    unsigned ph = 0;
    gbar(cta, ++ph);   // init visible everywhere

    // ---------------- per-thread setup ----------------
    float* wbase  = g_state + shot*4*Fc;
    float* pybase = wbase + 2*Fc;
    const float* v2 = g_state + 8*Fc;
    const float* amp_s = amp + shot*NSRCc*NTc;

    const float iH  = 1.0f / Hc;
    const float iH2 = 1.0f / (Hc*Hc);
    const float C1A =  0.66666666666666666f, C1B = -0.08333333333333333f;
    const float C2A =  1.33333333333333333f, C2B = -0.08333333333333333f, C2C = -2.5f;

    const int  x   = tid;
    const bool act = (tid < NP);

    float ayr[HR], byr[HR];
    #pragma unroll
    for (int r = 0; r < HR; r++) {
        int y = y0 - 2 + r;
        bool in = (y >= 0 && y < NP);
        ayr[r] = in ? g_a[y] : 0.0f;
        byr[r] = in ? g_b[y] : 0.0f;
    }
    const float axv = act ? g_a[x] : 0.0f;
    const float bxv = act ? g_b[x] : 0.0f;

    bool srow[RPC];
    #pragma unroll
    for (int r2 = 0; r2 < RPC; r2++) {
        bool s = false;
        #pragma unroll
        for (int j = 0; j < NSRCc; j++) s = s || ((sh_key[j] >> 9) == (y0 + r2));
        srow[r2] = s;
    }
    const int nrec = sh_rn;

    float psr[RPC], zyr[RPC], zxr[RPC], wold[RPC];
    #pragma unroll
    for (int r2 = 0; r2 < RPC; r2++) { psr[r2]=0.f; zyr[r2]=0.f; zxr[r2]=0.f; wold[r2]=0.f; }

    int cur = 0;

    // ---------------- time loop: ONE grid barrier per step ----------------
    for (int t = 0; t < NTc; t++) {
        const float* wfc = wbase + cur*Fc;
        float*       wst = wbase + (cur^1)*Fc;
        const int pb = t & 1;
        const float* pyold = pybase + (pb^1)*Fc;
        float*       pynew = pybase + pb*Fc;

        float s1[RPC], s2[RPC], cen[RPC];

        if (act) {
            // Column of wfc at this x: rows y0-4 .. y0+8 (13 independent L2 loads)
            float c[CR];
            #pragma unroll
            for (int k = 0; k < CR; k++)
                c[k] = __ldcg(wfc + IDX(y0 - 4 + k, x));
            // psiy halo (old values from neighbors), batched early for MLP
            float poh[4];
            {
                int yl1 = y0 - 2, yl2 = y0 - 1, yh1 = y0 + RPC, yh2 = y0 + RPC + 1;
                poh[0] = (yl1 >= 0) ? __ldcg(pyold + IDX(yl1, x)) : 0.0f;
                poh[1] = (yl2 >= 0) ? __ldcg(pyold + IDX(yl2, x)) : 0.0f;
                poh[2] = (yh1 < NP) ? __ldcg(pyold + IDX(yh1, x)) : 0.0f;
                poh[3] = (yh2 < NP) ? __ldcg(pyold + IDX(yh2, x)) : 0.0f;
            }

            // psiy update for 9 rows (owned + recomputed halo)
            float py[HR];
            #pragma unroll
            for (int r = 0; r < HR; r++) {
                int y = y0 - 2 + r;
                float dwdy = (C1A*(c[r+3]-c[r+1]) + C1B*(c[r+4]-c[r])) * iH;
                float po;
                if (r == 0) po = poh[0];
                else if (r == 1) po = poh[1];
                else if (r == HR-2) po = poh[2];
                else if (r == HR-1) po = poh[3];
                else po = psr[r-2];
                float pn = byr[r]*po + ayr[r]*dwdy;
                if (y < 0 || y >= NP) pn = 0.0f;
                py[r] = pn;
            }
            #pragma unroll
            for (int r2 = 0; r2 < RPC; r2++) {
                psr[r2] = py[r2+2];
                pynew[IDX(y0 + r2, x)] = py[r2+2];
            }

            // Owned rows: second derivatives, dpsiydy, psix update (smem)
            #pragma unroll
            for (int r2 = 0; r2 < RPC; r2++) {
                int m = r2 + 4;
                int p = IDX(y0 + r2, x);
                float b1 = wfc[p-1], b2 = wfc[p+1], b3 = wfc[p-2], b4 = wfc[p+2];
                float d2y  = (C2C*c[m] + C2A*(c[m-1]+c[m+1]) + C2B*(c[m-2]+c[m+2])) * iH2;
                float d2x  = (C2C*c[m] + C2A*(b1+b2)       + C2B*(b3+b4))         * iH2;
                float dwdx = (C1A*(b2-b1) + C1B*(b4-b3)) * iH;
                float dpy  = (C1A*(py[r2+3]-py[r2+1]) + C1B*(py[r2+4]-py[r2])) * iH;
                float pxn  = bxv*psix_s[r2][x+4] + axv*dwdx;
                psix_s[r2][x+4] = pxn;
                s1[r2] = d2y + dpy;
                s2[r2] = d2x;
                cen[r2] = c[m];
            }
        }
        __syncthreads();   // psix taps ready

        if (act) {
            #pragma unroll
            for (int r2 = 0; r2 < RPC; r2++) {
                int y = y0 + r2;
                int p = IDX(y, x);
                float dpx = (C1A*(psix_s[r2][x+5]-psix_s[r2][x+3])
                           + C1B*(psix_s[r2][x+6]-psix_s[r2][x+2])) * iH;
                float ayv = ayr[r2+2], byv = byr[r2+2];
                float zyv = byv*zyr[r2] + ayv*s1[r2];             zyr[r2] = zyv;
                float zxv = bxv*zxr[r2] + axv*(s2[r2] + dpx);     zxr[r2] = zxv;
                float lap = s1[r2] + s2[r2] + dpx + zyv + zxv;
                float wnew = 2.0f*cen[r2] - wold[r2] + v2[p]*lap;
                if (srow[r2]) {
                    int key = (y << 9) | x;
                    #pragma unroll
                    for (int j = 0; j < NSRCc; j++)
                        if (sh_key[j] == key) wnew += sh_scale[j] * amp_s[j*NTc + t];
                }
                wold[r2] = cen[r2];
                wst[p] = wnew;
                // owner-writes receiver recording (removes post-barrier gather)
                for (int j = 0; j < nrec; j++)
                    if (sh_rr2[j] == r2 && sh_rx[j] == x)
                        out[sh_ro[j]*NTc + t] = wnew;
            }
        }

        gbar(cta, ++ph);   // step complete everywhere
        cur ^= 1;
    }
}

extern "C" void kernel_launch(void* const* d_in, const int* in_sizes, int n_in,
                              void* d_out, int out_size)
{
    const float* v    = (const float*)d_in[0];
    const float* amp  = (const float*)d_in[1];
    const void*  sloc = d_in[2];
    const void*  rloc = d_in[3];
    wave_kernel<<<NCTA, TPB>>>(v, amp, sloc, rloc, (float*)d_out);
}